// round 9
// baseline (speedup 1.0000x reference)
#include <cuda_runtime.h>
#include <math.h>
#include <stdint.h>

#define DIMV 1920
#define T_TXT 226
#define SVID 2048
#define SEQ 2274
#define NH 30
#define HD 64

// ---------------- scratch (device globals; no allocation allowed) ----------------
__device__ float g_hs[SEQ * DIMV];        // concat(encoder, hidden)
__device__ float g_q[NH * SEQ * HD];      // head-major
__device__ float g_k[NH * SEQ * HD];
__device__ float g_v[NH * SEQ * HD];
__device__ float g_attn[SEQ * DIMV];      // attention output [s][dim] (+conv branch)
__device__ float g_gelu[256 * 128 * 8];   // conv1+gelu intermediate [p][r][f]

// ---------------- tf32 helpers ----------------
__device__ __forceinline__ uint32_t f2tf32(float x) {
    uint32_t r;
    asm("cvt.rna.tf32.f32 %0, %1;" : "=r"(r) : "f"(x));
    return r;
}
__device__ __forceinline__ void split_tf32(float x, uint32_t& hi, uint32_t& lo) {
    hi = f2tf32(x);
    lo = f2tf32(x - __uint_as_float(hi));
}
__device__ __forceinline__ void mma_tf32(float* d, const uint32_t* a, const uint32_t* b) {
    asm volatile(
        "mma.sync.aligned.m16n8k8.row.col.f32.tf32.tf32.f32 "
        "{%0,%1,%2,%3}, {%4,%5,%6,%7}, {%8,%9}, {%0,%1,%2,%3};"
        : "+f"(d[0]), "+f"(d[1]), "+f"(d[2]), "+f"(d[3])
        : "r"(a[0]), "r"(a[1]), "r"(a[2]), "r"(a[3]), "r"(b[0]), "r"(b[1]));
}

// ---------------- 3xTF32 tensor-core NT GEMM, pipelined, split-once smem ----------------
// C = A(MxK) @ B(NxK)^T + bias
// MODE 0: head-major qkv epilogue; MODE 1: row-remap epilogue.
// Requires K % 16 == 0, N % 128 == 0.
#define KC 16
template <int MODE>
__global__ void __launch_bounds__(256) gemm_tf32(
    const float* __restrict__ A, const float* __restrict__ B,
    const float* __restrict__ bias, float* __restrict__ C,
    int M, int N, int K, long long out_limit)
{
    // packed (hi,lo) tf32 pairs; row stride 20 uint2 (16 data + 4 pad)
    __shared__ __align__(16) uint2 Apk[128][20];
    __shared__ __align__(16) uint2 Bpk[128][20];

    int tid  = threadIdx.x;
    int lane = tid & 31;
    int warp = tid >> 5;
    int wm = (warp >> 1) * 32;
    int wn = (warp & 1) * 64;
    int gr = lane >> 2;
    int gc = lane & 3;

    int m0 = blockIdx.x * 128, n0 = blockIdx.y * 128;

    float acc[2][8][4];
#pragma unroll
    for (int i = 0; i < 2; i++)
#pragma unroll
        for (int j = 0; j < 8; j++)
#pragma unroll
            for (int t = 0; t < 4; t++) acc[i][j][t] = 0.f;

    // prefetch registers: 2 float4 per matrix per thread (128 rows x 16 k / 256 thr)
    float4 ra[2], rb[2];
#pragma unroll
    for (int i = 0; i < 2; i++) {
        int idx = tid + i * 256;            // 0..511
        int row = idx >> 2, c4 = idx & 3;   // row 0..127, c4 0..3
        ra[i] = make_float4(0.f, 0.f, 0.f, 0.f);
        if (m0 + row < M)
            ra[i] = *(const float4*)&A[(size_t)(m0 + row) * K + c4 * 4];
        rb[i] = *(const float4*)&B[(size_t)(n0 + row) * K + c4 * 4];
    }

    int NC = K / KC;
    for (int c = 0; c < NC; c++) {
        __syncthreads();   // previous compute done before smem overwrite
        // split once and store packed (hi,lo)
#pragma unroll
        for (int i = 0; i < 2; i++) {
            int idx = tid + i * 256;
            int row = idx >> 2, c4 = idx & 3;
            const float* av = (const float*)&ra[i];
            const float* bv = (const float*)&rb[i];
            uint32_t h0, l0, h1, l1;
#pragma unroll
            for (int p = 0; p < 2; p++) {
                split_tf32(av[p * 2],     h0, l0);
                split_tf32(av[p * 2 + 1], h1, l1);
                *(uint4*)&Apk[row][c4 * 4 + p * 2] = make_uint4(h0, l0, h1, l1);
                split_tf32(bv[p * 2],     h0, l0);
                split_tf32(bv[p * 2 + 1], h1, l1);
                *(uint4*)&Bpk[row][c4 * 4 + p * 2] = make_uint4(h0, l0, h1, l1);
            }
        }
        __syncthreads();
        // issue next chunk's global loads (latency hidden behind compute)
        if (c + 1 < NC) {
            int k0 = (c + 1) * KC;
#pragma unroll
            for (int i = 0; i < 2; i++) {
                int idx = tid + i * 256;
                int row = idx >> 2, c4 = idx & 3;
                ra[i] = make_float4(0.f, 0.f, 0.f, 0.f);
                if (m0 + row < M)
                    ra[i] = *(const float4*)&A[(size_t)(m0 + row) * K + k0 + c4 * 4];
                rb[i] = *(const float4*)&B[(size_t)(n0 + row) * K + k0 + c4 * 4];
            }
        }
        // compute: 2 k-steps of 8
#pragma unroll
        for (int kk = 0; kk < 2; kk++) {
            int kb = kk * 8;
            uint2 af[2][4];
#pragma unroll
            for (int mf = 0; mf < 2; mf++) {
                int r = wm + mf * 16 + gr;
                af[mf][0] = Apk[r][kb + gc];
                af[mf][1] = Apk[r + 8][kb + gc];
                af[mf][2] = Apk[r][kb + gc + 4];
                af[mf][3] = Apk[r + 8][kb + gc + 4];
            }
            uint2 bf[8][2];
#pragma unroll
            for (int nf = 0; nf < 8; nf++) {
                int cc = wn + nf * 8 + gr;
                bf[nf][0] = Bpk[cc][kb + gc];
                bf[nf][1] = Bpk[cc][kb + gc + 4];
            }
#pragma unroll
            for (int mf = 0; mf < 2; mf++) {
                uint32_t ah[4] = { af[mf][0].x, af[mf][1].x, af[mf][2].x, af[mf][3].x };
                uint32_t al[4] = { af[mf][0].y, af[mf][1].y, af[mf][2].y, af[mf][3].y };
#pragma unroll
                for (int nf = 0; nf < 8; nf++) {
                    uint32_t bh[2] = { bf[nf][0].x, bf[nf][1].x };
                    uint32_t bl[2] = { bf[nf][0].y, bf[nf][1].y };
                    mma_tf32(acc[mf][nf], ah, bh);
                    mma_tf32(acc[mf][nf], al, bh);
                    mma_tf32(acc[mf][nf], ah, bl);
                }
            }
        }
    }

    // epilogue: fragment c0:(r,c) c1:(r,c+1) c2:(r+8,c) c3:(r+8,c+1)
#pragma unroll
    for (int mf = 0; mf < 2; mf++) {
        int rbase = m0 + wm + mf * 16 + gr;
#pragma unroll
        for (int nf = 0; nf < 8; nf++) {
            int cbase = n0 + wn + nf * 8 + gc * 2;
#pragma unroll
            for (int half = 0; half < 2; half++) {
                int m = rbase + half * 8;
                if (m >= M) continue;
#pragma unroll
                for (int jj = 0; jj < 2; jj++) {
                    int n = cbase + jj;
                    float val = acc[mf][nf][half * 2 + jj] + bias[n];
                    if (MODE == 0) {
                        C[((n >> 6) * SEQ + m) * 64 + (n & 63)] = val;
                    } else {
                        int r = (m >= T_TXT) ? (m - T_TXT) : (SVID + m);
                        long long idx = (long long)r * N + n;
                        if (idx < out_limit) C[idx] = val;
                    }
                }
            }
        }
    }
}

// ---------------- per-(head,pos) LayerNorm(HD=64) + RoPE on video rows ----------------
__global__ void __launch_bounds__(128) ln_rope_kernel(
    float* __restrict__ qbuf, float* __restrict__ kbuf,
    const float* __restrict__ cosb, const float* __restrict__ sinb,
    const float* __restrict__ nqw, const float* __restrict__ nqb,
    const float* __restrict__ nkw, const float* __restrict__ nkb)
{
    int warp = threadIdx.x >> 5, lane = threadIdx.x & 31;
    int row = blockIdx.x * 4 + warp;
    const int ROWS = NH * SEQ;
    if (row >= 2 * ROWS) return;
    int zk = (row >= ROWS) ? 1 : 0;
    int rem = zk ? (row - ROWS) : row;
    int s = rem % SEQ;
    float* x = (zk ? kbuf : qbuf) + rem * HD;
    const float* wgt = zk ? nkw : nqw;
    const float* bia = zk ? nkb : nqb;

    float v0 = x[2 * lane], v1 = x[2 * lane + 1];
    float sum = v0 + v1;
#pragma unroll
    for (int o = 16; o; o >>= 1) sum += __shfl_xor_sync(0xffffffffu, sum, o);
    float mu = sum * (1.f / 64.f);
    float d0 = v0 - mu, d1 = v1 - mu;
    float vs = d0 * d0 + d1 * d1;
#pragma unroll
    for (int o = 16; o; o >>= 1) vs += __shfl_xor_sync(0xffffffffu, vs, o);
    float rstd = rsqrtf(vs * (1.f / 64.f) + 1e-6f);
    float y0 = d0 * rstd * wgt[2 * lane] + bia[2 * lane];
    float y1 = d1 * rstd * wgt[2 * lane + 1] + bia[2 * lane + 1];
    if (s >= T_TXT) {
        int sv = s - T_TXT;
        float c0 = cosb[sv * HD + 2 * lane], c1 = cosb[sv * HD + 2 * lane + 1];
        float sn0 = sinb[sv * HD + 2 * lane], sn1 = sinb[sv * HD + 2 * lane + 1];
        float r0v = y0 * c0 - y1 * sn0;
        float r1v = y1 * c1 + y0 * sn1;
        y0 = r0v; y1 = r1v;
    }
    x[2 * lane] = y0;
    x[2 * lane + 1] = y1;
}

// ---------------- flash attention, 3xTF32 tensor cores, BQ=64 BKV=32 ----------------
__global__ void __launch_bounds__(256) attention_mma_kernel(
    const float* __restrict__ q, const float* __restrict__ k,
    const float* __restrict__ v, float* __restrict__ attn)
{
    __shared__ __align__(16) float Qs[64][68];   // [q][d]
    __shared__ __align__(16) float Ks[32][68];   // [kv][d]
    __shared__ __align__(16) float Vs[64][36];   // [d][kv]  (transposed)
    __shared__ __align__(16) float Ps[64][36];   // [q][kv]  scores / probs
    __shared__ float ms[64], ls[64], cs[64];

    int tid  = threadIdx.x;
    int lane = tid & 31;
    int warp = tid >> 5;
    int gr = lane >> 2;
    int gc = lane & 3;
    int wm   = (warp >> 1) * 16;
    int wn16 = (warp & 1) * 16;
    int wn32 = (warp & 1) * 32;

    int h  = blockIdx.y;
    int q0 = blockIdx.x * 64;
    const float* qh = q + (size_t)(h * SEQ) * HD;
    const float* kh = k + (size_t)(h * SEQ) * HD;
    const float* vh = v + (size_t)(h * SEQ) * HD;

    {
        int r = tid >> 2, c16 = (tid & 3) * 16;
#pragma unroll
        for (int j = 0; j < 4; j++) {
            float4 val = make_float4(0.f, 0.f, 0.f, 0.f);
            if (q0 + r < SEQ)
                val = *(const float4*)&qh[(size_t)(q0 + r) * HD + c16 + j * 4];
            *(float4*)&Qs[r][c16 + j * 4] = val;
        }
    }
    if (tid < 64) { ms[tid] = -1e30f; ls[tid] = 0.f; }
    __syncthreads();

    uint32_t q_hi[8][4], q_lo[8][4];
#pragma unroll
    for (int ks = 0; ks < 8; ks++) {
        int kb = ks * 8;
        split_tf32(Qs[wm + gr][kb + gc],         q_hi[ks][0], q_lo[ks][0]);
        split_tf32(Qs[wm + gr + 8][kb + gc],     q_hi[ks][1], q_lo[ks][1]);
        split_tf32(Qs[wm + gr][kb + gc + 4],     q_hi[ks][2], q_lo[ks][2]);
        split_tf32(Qs[wm + gr + 8][kb + gc + 4], q_hi[ks][3], q_lo[ks][3]);
    }

    float oacc[4][4];
#pragma unroll
    for (int i = 0; i < 4; i++)
#pragma unroll
        for (int j = 0; j < 4; j++) oacc[i][j] = 0.f;

    for (int kv0 = 0; kv0 < SEQ; kv0 += 32) {
        int jmax = min(32, SEQ - kv0);

        {
            int r = tid >> 3, c8 = (tid & 7) * 8;
            float4 k0v = make_float4(0.f, 0.f, 0.f, 0.f);
            float4 k1v = make_float4(0.f, 0.f, 0.f, 0.f);
            if (r < jmax) {
                k0v = *(const float4*)&kh[(size_t)(kv0 + r) * HD + c8];
                k1v = *(const float4*)&kh[(size_t)(kv0 + r) * HD + c8 + 4];
            }
            *(float4*)&Ks[r][c8]     = k0v;
            *(float4*)&Ks[r][c8 + 4] = k1v;
        }
        {
            int kvr = tid & 31, dbase = (tid >> 5) * 8;
            float4 v0 = make_float4(0.f, 0.f, 0.f, 0.f);
            float4 v1 = make_float4(0.f, 0.f, 0.f, 0.f);
            if (kvr < jmax) {
                v0 = *(const float4*)&vh[(size_t)(kv0 + kvr) * HD + dbase];
                v1 = *(const float4*)&vh[(size_t)(kv0 + kvr) * HD + dbase + 4];
            }
            Vs[dbase + 0][kvr] = v0.x; Vs[dbase + 1][kvr] = v0.y;
            Vs[dbase + 2][kvr] = v0.z; Vs[dbase + 3][kvr] = v0.w;
            Vs[dbase + 4][kvr] = v1.x; Vs[dbase + 5][kvr] = v1.y;
            Vs[dbase + 6][kvr] = v1.z; Vs[dbase + 7][kvr] = v1.w;
        }
        __syncthreads();

        float sacc[2][4] = {};
#pragma unroll
        for (int ks = 0; ks < 8; ks++) {
            int kb = ks * 8;
#pragma unroll
            for (int nf = 0; nf < 2; nf++) {
                int n = wn16 + nf * 8 + gr;
                uint32_t bh[2], bl[2];
                split_tf32(Ks[n][kb + gc],     bh[0], bl[0]);
                split_tf32(Ks[n][kb + gc + 4], bh[1], bl[1]);
                mma_tf32(sacc[nf], q_hi[ks], bh);
                mma_tf32(sacc[nf], q_lo[ks], bh);
                mma_tf32(sacc[nf], q_hi[ks], bl);
            }
        }
#pragma unroll
        for (int nf = 0; nf < 2; nf++) {
            int n2 = wn16 + nf * 8 + gc * 2;
            Ps[wm + gr][n2]         = sacc[nf][0] * 0.125f;
            Ps[wm + gr][n2 + 1]     = sacc[nf][1] * 0.125f;
            Ps[wm + gr + 8][n2]     = sacc[nf][2] * 0.125f;
            Ps[wm + gr + 8][n2 + 1] = sacc[nf][3] * 0.125f;
        }
        __syncthreads();

        {
            int row = tid >> 2, qd = tid & 3;
            int jb = qd * 8;
            float mx = -1e30f;
#pragma unroll
            for (int j = 0; j < 8; j++)
                if (jb + j < jmax) mx = fmaxf(mx, Ps[row][jb + j]);
            mx = fmaxf(mx, __shfl_xor_sync(0xffffffffu, mx, 1));
            mx = fmaxf(mx, __shfl_xor_sync(0xffffffffu, mx, 2));
            float mo = ms[row];
            float mxn = fmaxf(mo, mx);
            float sum = 0.f;
#pragma unroll
            for (int j = 0; j < 8; j++) {
                float p = (jb + j < jmax) ? __expf(Ps[row][jb + j] - mxn) : 0.f;
                Ps[row][jb + j] = p;
                sum += p;
            }
            sum += __shfl_xor_sync(0xffffffffu, sum, 1);
            sum += __shfl_xor_sync(0xffffffffu, sum, 2);
            if (qd == 0) {
                float c = __expf(mo - mxn);
                ms[row] = mxn;
                ls[row] = ls[row] * c + sum;
                cs[row] = c;
            }
        }
        __syncthreads();

        {
            float c_lo = cs[wm + gr], c_hi = cs[wm + gr + 8];
#pragma unroll
            for (int nf = 0; nf < 4; nf++) {
                oacc[nf][0] *= c_lo; oacc[nf][1] *= c_lo;
                oacc[nf][2] *= c_hi; oacc[nf][3] *= c_hi;
            }
#pragma unroll
            for (int ks = 0; ks < 4; ks++) {
                int kb = ks * 8;
                uint32_t a_hi[4], a_lo[4];
                split_tf32(Ps[wm + gr][kb + gc],         a_hi[0], a_lo[0]);
                split_tf32(Ps[wm + gr + 8][kb + gc],     a_hi[1], a_lo[1]);
                split_tf32(Ps[wm + gr][kb + gc + 4],     a_hi[2], a_lo[2]);
                split_tf32(Ps[wm + gr + 8][kb + gc + 4], a_hi[3], a_lo[3]);
#pragma unroll
                for (int nf = 0; nf < 4; nf++) {
                    int n = wn32 + nf * 8 + gr;
                    uint32_t bh[2], bl[2];
                    split_tf32(Vs[n][kb + gc],     bh[0], bl[0]);
                    split_tf32(Vs[n][kb + gc + 4], bh[1], bl[1]);
                    mma_tf32(oacc[nf], a_hi, bh);
                    mma_tf32(oacc[nf], a_lo, bh);
                    mma_tf32(oacc[nf], a_hi, bl);
                }
            }
        }
        __syncthreads();
    }

    {
        float inv0 = 1.f / ls[wm + gr];
        float inv1 = 1.f / ls[wm + gr + 8];
        int s0 = q0 + wm + gr;
        int s1 = s0 + 8;
#pragma unroll
        for (int nf = 0; nf < 4; nf++) {
            int n2 = wn32 + nf * 8 + gc * 2;
            if (s0 < SEQ) {
                attn[(size_t)s0 * DIMV + h * HD + n2]     = oacc[nf][0] * inv0;
                attn[(size_t)s0 * DIMV + h * HD + n2 + 1] = oacc[nf][1] * inv0;
            }
            if (s1 < SEQ) {
                attn[(size_t)s1 * DIMV + h * HD + n2]     = oacc[nf][2] * inv1;
                attn[(size_t)s1 * DIMV + h * HD + n2 + 1] = oacc[nf][3] * inv1;
            }
        }
    }
}

// ---------------- conv1 (DIM->RANK, k=3, pad 1 over F=8) + exact GELU ----------------
__global__ void __launch_bounds__(128) conv1_gelu_kernel(
    const float* __restrict__ hidden, const float* __restrict__ w1,
    float* __restrict__ gel)
{
    __shared__ float xs[256][9];
    int p = blockIdx.x;
    int r = threadIdx.x;
    float acc[8] = {};
    for (int d0 = 0; d0 < DIMV; d0 += 256) {
        int dmax = min(256, DIMV - d0);
        for (int i = threadIdx.x; i < 2048; i += 128) {
            int d = i & 255, f = i >> 8;
            xs[d][f] = (d < dmax) ? hidden[(f * 256 + p) * DIMV + d0 + d] : 0.f;
        }
        __syncthreads();
#pragma unroll 2
        for (int d = 0; d < dmax; d++) {
            const float* w = w1 + r * (DIMV * 3) + (d0 + d) * 3;
            float w0 = w[0], wm = w[1], w2 = w[2];
            float xp[10];
            xp[0] = 0.f; xp[9] = 0.f;
#pragma unroll
            for (int f = 0; f < 8; f++) xp[f + 1] = xs[d][f];
#pragma unroll
            for (int f = 0; f < 8; f++)
                acc[f] += w0 * xp[f] + wm * xp[f + 1] + w2 * xp[f + 2];
        }
        __syncthreads();
    }
#pragma unroll
    for (int f = 0; f < 8; f++) {
        float x = acc[f];
        float g = 0.5f * x * (1.f + erff(x * 0.70710678118654752f));
        gel[(p * 128 + r) * 8 + f] = g;
    }
}

// ---------------- conv2 (RANK->DIM, k=3, pad 1) fused add into attn buffer ----------------
__global__ void __launch_bounds__(256) conv2_add_kernel(
    const float* __restrict__ w2, const float* __restrict__ gel,
    float* __restrict__ attn)
{
    __shared__ float gs[128][10];
    int p = blockIdx.x;
    int tid = threadIdx.x;
    for (int i = tid; i < 1024; i += 256) {
        int rr = i >> 3, f = i & 7;
        gs[rr][f + 1] = gel[(p * 128 + rr) * 8 + f];
    }
    if (tid < 128) { gs[tid][0] = 0.f; gs[tid][9] = 0.f; }
    __syncthreads();

    for (int d = tid; d < DIMV; d += 256) {
        float acc[8] = {};
        const float* w = w2 + d * 384;
#pragma unroll 2
        for (int rr = 0; rr < 128; rr++) {
            float w0 = w[rr * 3], wm = w[rr * 3 + 1], w2v = w[rr * 3 + 2];
#pragma unroll
            for (int f = 0; f < 8; f++)
                acc[f] += w0 * gs[rr][f] + wm * gs[rr][f + 1] + w2v * gs[rr][f + 2];
        }
#pragma unroll
        for (int f = 0; f < 8; f++) {
            int s = T_TXT + f * 256 + p;
            attn[s * DIMV + d] += acc[f];
        }
    }
}

// ---------------- launch ----------------
extern "C" void kernel_launch(void* const* d_in, const int* in_sizes, int n_in,
                              void* d_out, int out_size)
{
    const float* hidden = (const float*)d_in[0];
    const float* enc    = (const float*)d_in[1];
    const float* cosb   = (const float*)d_in[2];
    const float* sinb   = (const float*)d_in[3];
    const float* qw = (const float*)d_in[4];
    const float* qb = (const float*)d_in[5];
    const float* kw = (const float*)d_in[6];
    const float* kb = (const float*)d_in[7];
    const float* vw = (const float*)d_in[8];
    const float* vb = (const float*)d_in[9];
    const float* nqw = (const float*)d_in[10];
    const float* nqb = (const float*)d_in[11];
    const float* nkw = (const float*)d_in[12];
    const float* nkb = (const float*)d_in[13];
    const float* w1 = (const float*)d_in[14];
    const float* w2 = (const float*)d_in[15];
    const float* ow = (const float*)d_in[16];
    const float* ob = (const float*)d_in[17];

    float *hs, *q, *k, *v, *attn, *gel;
    cudaGetSymbolAddress((void**)&hs,   g_hs);
    cudaGetSymbolAddress((void**)&q,    g_q);
    cudaGetSymbolAddress((void**)&k,    g_k);
    cudaGetSymbolAddress((void**)&v,    g_v);
    cudaGetSymbolAddress((void**)&attn, g_attn);
    cudaGetSymbolAddress((void**)&gel,  g_gelu);

    cudaMemcpyAsync(hs, enc, (size_t)T_TXT * DIMV * sizeof(float),
                    cudaMemcpyDeviceToDevice, 0);
    cudaMemcpyAsync(hs + T_TXT * DIMV, hidden, (size_t)SVID * DIMV * sizeof(float),
                    cudaMemcpyDeviceToDevice, 0);

    dim3 gg((SEQ + 127) / 128, DIMV / 128);   // 18 x 15
    gemm_tf32<0><<<gg, 256>>>(hs, qw, qb, q, SEQ, DIMV, DIMV, 0);
    gemm_tf32<0><<<gg, 256>>>(hs, kw, kb, k, SEQ, DIMV, DIMV, 0);
    gemm_tf32<0><<<gg, 256>>>(hs, vw, vb, v, SEQ, DIMV, DIMV, 0);

    ln_rope_kernel<<<(2 * NH * SEQ + 3) / 4, 128>>>(q, k, cosb, sinb, nqw, nqb, nkw, nkb);

    attention_mma_kernel<<<dim3((SEQ + 63) / 64, NH), 256>>>(q, k, v, attn);

    conv1_gelu_kernel<<<256, 128>>>(hidden, w1, gel);
    conv2_add_kernel<<<256, 256>>>(w2, gel, attn);

    gemm_tf32<1><<<gg, 256>>>(attn, ow, ob, (float*)d_out, SEQ, DIMV, DIMV,
                              (long long)out_size);
}

// round 10
// speedup vs baseline: 1.0043x; 1.0043x over previous
#include <cuda_runtime.h>
#include <math.h>
#include <stdint.h>

#define DIMV 1920
#define T_TXT 226
#define SVID 2048
#define SEQ 2274
#define NH 30
#define HD 64

// ---------------- scratch (device globals; no allocation allowed) ----------------
__device__ float g_hs[SEQ * DIMV];        // concat(encoder, hidden)
__device__ float g_q[NH * SEQ * HD];      // head-major
__device__ float g_k[NH * SEQ * HD];
__device__ float g_v[NH * SEQ * HD];
__device__ float g_attn[SEQ * DIMV];      // attention output [s][dim] (+conv branch)
__device__ float g_gelu[256 * 128 * 8];   // conv1+gelu intermediate [p][r][f]

// ---------------- tf32 helpers ----------------
__device__ __forceinline__ uint32_t f2tf32(float x) {
    uint32_t r;
    asm("cvt.rna.tf32.f32 %0, %1;" : "=r"(r) : "f"(x));
    return r;
}
__device__ __forceinline__ void split_tf32(float x, uint32_t& hi, uint32_t& lo) {
    hi = f2tf32(x);
    lo = f2tf32(x - __uint_as_float(hi));
}
__device__ __forceinline__ void mma_tf32(float* d, const uint32_t* a, const uint32_t* b) {
    asm volatile(
        "mma.sync.aligned.m16n8k8.row.col.f32.tf32.tf32.f32 "
        "{%0,%1,%2,%3}, {%4,%5,%6,%7}, {%8,%9}, {%0,%1,%2,%3};"
        : "+f"(d[0]), "+f"(d[1]), "+f"(d[2]), "+f"(d[3])
        : "r"(a[0]), "r"(a[1]), "r"(a[2]), "r"(a[3]), "r"(b[0]), "r"(b[1]));
}

// ---------------- 3xTF32 tensor-core NT GEMM, pipelined, split-once smem ----------------
// C = A(MxK) @ B(NxK)^T + bias
// MODE 0: head-major qkv epilogue; MODE 1: row-remap epilogue.
// Requires K % 16 == 0, N % 128 == 0.
#define KC 16
template <int MODE>
__global__ void __launch_bounds__(256) gemm_tf32(
    const float* __restrict__ A, const float* __restrict__ B,
    const float* __restrict__ bias, float* __restrict__ C,
    int M, int N, int K, long long out_limit)
{
    // packed (hi,lo) tf32 pairs; row stride 20 uint2 (16 data + 4 pad)
    __shared__ __align__(16) uint2 Apk[128][20];
    __shared__ __align__(16) uint2 Bpk[128][20];

    int tid  = threadIdx.x;
    int lane = tid & 31;
    int warp = tid >> 5;
    int wm = (warp >> 1) * 32;
    int wn = (warp & 1) * 64;
    int gr = lane >> 2;
    int gc = lane & 3;

    int m0 = blockIdx.x * 128, n0 = blockIdx.y * 128;

    float acc[2][8][4];
#pragma unroll
    for (int i = 0; i < 2; i++)
#pragma unroll
        for (int j = 0; j < 8; j++)
#pragma unroll
            for (int t = 0; t < 4; t++) acc[i][j][t] = 0.f;

    // prefetch registers: 2 float4 per matrix per thread (128 rows x 16 k / 256 thr)
    float4 ra[2], rb[2];
#pragma unroll
    for (int i = 0; i < 2; i++) {
        int idx = tid + i * 256;            // 0..511
        int row = idx >> 2, c4 = idx & 3;   // row 0..127, c4 0..3
        ra[i] = make_float4(0.f, 0.f, 0.f, 0.f);
        if (m0 + row < M)
            ra[i] = *(const float4*)&A[(size_t)(m0 + row) * K + c4 * 4];
        rb[i] = *(const float4*)&B[(size_t)(n0 + row) * K + c4 * 4];
    }

    int NC = K / KC;
    for (int c = 0; c < NC; c++) {
        __syncthreads();   // previous compute done before smem overwrite
        // split once and store packed (hi,lo)
#pragma unroll
        for (int i = 0; i < 2; i++) {
            int idx = tid + i * 256;
            int row = idx >> 2, c4 = idx & 3;
            const float* av = (const float*)&ra[i];
            const float* bv = (const float*)&rb[i];
            uint32_t h0, l0, h1, l1;
#pragma unroll
            for (int p = 0; p < 2; p++) {
                split_tf32(av[p * 2],     h0, l0);
                split_tf32(av[p * 2 + 1], h1, l1);
                *(uint4*)&Apk[row][c4 * 4 + p * 2] = make_uint4(h0, l0, h1, l1);
                split_tf32(bv[p * 2],     h0, l0);
                split_tf32(bv[p * 2 + 1], h1, l1);
                *(uint4*)&Bpk[row][c4 * 4 + p * 2] = make_uint4(h0, l0, h1, l1);
            }
        }
        __syncthreads();
        // issue next chunk's global loads (latency hidden behind compute)
        if (c + 1 < NC) {
            int k0 = (c + 1) * KC;
#pragma unroll
            for (int i = 0; i < 2; i++) {
                int idx = tid + i * 256;
                int row = idx >> 2, c4 = idx & 3;
                ra[i] = make_float4(0.f, 0.f, 0.f, 0.f);
                if (m0 + row < M)
                    ra[i] = *(const float4*)&A[(size_t)(m0 + row) * K + k0 + c4 * 4];
                rb[i] = *(const float4*)&B[(size_t)(n0 + row) * K + k0 + c4 * 4];
            }
        }
        // compute: 2 k-steps of 8
#pragma unroll
        for (int kk = 0; kk < 2; kk++) {
            int kb = kk * 8;
            uint2 af[2][4];
#pragma unroll
            for (int mf = 0; mf < 2; mf++) {
                int r = wm + mf * 16 + gr;
                af[mf][0] = Apk[r][kb + gc];
                af[mf][1] = Apk[r + 8][kb + gc];
                af[mf][2] = Apk[r][kb + gc + 4];
                af[mf][3] = Apk[r + 8][kb + gc + 4];
            }
            uint2 bf[8][2];
#pragma unroll
            for (int nf = 0; nf < 8; nf++) {
                int cc = wn + nf * 8 + gr;
                bf[nf][0] = Bpk[cc][kb + gc];
                bf[nf][1] = Bpk[cc][kb + gc + 4];
            }
#pragma unroll
            for (int mf = 0; mf < 2; mf++) {
                uint32_t ah[4] = { af[mf][0].x, af[mf][1].x, af[mf][2].x, af[mf][3].x };
                uint32_t al[4] = { af[mf][0].y, af[mf][1].y, af[mf][2].y, af[mf][3].y };
#pragma unroll
                for (int nf = 0; nf < 8; nf++) {
                    uint32_t bh[2] = { bf[nf][0].x, bf[nf][1].x };
                    uint32_t bl[2] = { bf[nf][0].y, bf[nf][1].y };
                    mma_tf32(acc[mf][nf], ah, bh);
                    mma_tf32(acc[mf][nf], al, bh);
                    mma_tf32(acc[mf][nf], ah, bl);
                }
            }
        }
    }

    // epilogue: fragment c0:(r,c) c1:(r,c+1) c2:(r+8,c) c3:(r+8,c+1)
#pragma unroll
    for (int mf = 0; mf < 2; mf++) {
        int rbase = m0 + wm + mf * 16 + gr;
#pragma unroll
        for (int nf = 0; nf < 8; nf++) {
            int cbase = n0 + wn + nf * 8 + gc * 2;
#pragma unroll
            for (int half = 0; half < 2; half++) {
                int m = rbase + half * 8;
                if (m >= M) continue;
#pragma unroll
                for (int jj = 0; jj < 2; jj++) {
                    int n = cbase + jj;
                    float val = acc[mf][nf][half * 2 + jj] + bias[n];
                    if (MODE == 0) {
                        C[((n >> 6) * SEQ + m) * 64 + (n & 63)] = val;
                    } else {
                        int r = (m >= T_TXT) ? (m - T_TXT) : (SVID + m);
                        long long idx = (long long)r * N + n;
                        if (idx < out_limit) C[idx] = val;
                    }
                }
            }
        }
    }
}

// ---------------- per-(head,pos) LayerNorm(HD=64) + RoPE on video rows ----------------
__global__ void __launch_bounds__(128) ln_rope_kernel(
    float* __restrict__ qbuf, float* __restrict__ kbuf,
    const float* __restrict__ cosb, const float* __restrict__ sinb,
    const float* __restrict__ nqw, const float* __restrict__ nqb,
    const float* __restrict__ nkw, const float* __restrict__ nkb)
{
    int warp = threadIdx.x >> 5, lane = threadIdx.x & 31;
    int row = blockIdx.x * 4 + warp;
    const int ROWS = NH * SEQ;
    if (row >= 2 * ROWS) return;
    int zk = (row >= ROWS) ? 1 : 0;
    int rem = zk ? (row - ROWS) : row;
    int s = rem % SEQ;
    float* x = (zk ? kbuf : qbuf) + rem * HD;
    const float* wgt = zk ? nkw : nqw;
    const float* bia = zk ? nkb : nqb;

    float v0 = x[2 * lane], v1 = x[2 * lane + 1];
    float sum = v0 + v1;
#pragma unroll
    for (int o = 16; o; o >>= 1) sum += __shfl_xor_sync(0xffffffffu, sum, o);
    float mu = sum * (1.f / 64.f);
    float d0 = v0 - mu, d1 = v1 - mu;
    float vs = d0 * d0 + d1 * d1;
#pragma unroll
    for (int o = 16; o; o >>= 1) vs += __shfl_xor_sync(0xffffffffu, vs, o);
    float rstd = rsqrtf(vs * (1.f / 64.f) + 1e-6f);
    float y0 = d0 * rstd * wgt[2 * lane] + bia[2 * lane];
    float y1 = d1 * rstd * wgt[2 * lane + 1] + bia[2 * lane + 1];
    if (s >= T_TXT) {
        int sv = s - T_TXT;
        float c0 = cosb[sv * HD + 2 * lane], c1 = cosb[sv * HD + 2 * lane + 1];
        float sn0 = sinb[sv * HD + 2 * lane], sn1 = sinb[sv * HD + 2 * lane + 1];
        float r0v = y0 * c0 - y1 * sn0;
        float r1v = y1 * c1 + y0 * sn1;
        y0 = r0v; y1 = r1v;
    }
    x[2 * lane] = y0;
    x[2 * lane + 1] = y1;
}

// ---------------- flash attention, 3xTF32 tensor cores, BQ=64 BKV=32 ----------------
__global__ void __launch_bounds__(256) attention_mma_kernel(
    const float* __restrict__ q, const float* __restrict__ k,
    const float* __restrict__ v, float* __restrict__ attn)
{
    __shared__ __align__(16) float Qs[64][68];   // [q][d]
    __shared__ __align__(16) float Ks[32][68];   // [kv][d]
    __shared__ __align__(16) float Vs[64][36];   // [d][kv]  (transposed)
    __shared__ __align__(16) float Ps[64][36];   // [q][kv]  scores / probs
    __shared__ float ms[64], ls[64], cs[64];

    int tid  = threadIdx.x;
    int lane = tid & 31;
    int warp = tid >> 5;
    int gr = lane >> 2;
    int gc = lane & 3;
    int wm   = (warp >> 1) * 16;
    int wn16 = (warp & 1) * 16;
    int wn32 = (warp & 1) * 32;

    int h  = blockIdx.y;
    int q0 = blockIdx.x * 64;
    const float* qh = q + (size_t)(h * SEQ) * HD;
    const float* kh = k + (size_t)(h * SEQ) * HD;
    const float* vh = v + (size_t)(h * SEQ) * HD;

    {
        int r = tid >> 2, c16 = (tid & 3) * 16;
#pragma unroll
        for (int j = 0; j < 4; j++) {
            float4 val = make_float4(0.f, 0.f, 0.f, 0.f);
            if (q0 + r < SEQ)
                val = *(const float4*)&qh[(size_t)(q0 + r) * HD + c16 + j * 4];
            *(float4*)&Qs[r][c16 + j * 4] = val;
        }
    }
    if (tid < 64) { ms[tid] = -1e30f; ls[tid] = 0.f; }
    __syncthreads();

    uint32_t q_hi[8][4], q_lo[8][4];
#pragma unroll
    for (int ks = 0; ks < 8; ks++) {
        int kb = ks * 8;
        split_tf32(Qs[wm + gr][kb + gc],         q_hi[ks][0], q_lo[ks][0]);
        split_tf32(Qs[wm + gr + 8][kb + gc],     q_hi[ks][1], q_lo[ks][1]);
        split_tf32(Qs[wm + gr][kb + gc + 4],     q_hi[ks][2], q_lo[ks][2]);
        split_tf32(Qs[wm + gr + 8][kb + gc + 4], q_hi[ks][3], q_lo[ks][3]);
    }

    float oacc[4][4];
#pragma unroll
    for (int i = 0; i < 4; i++)
#pragma unroll
        for (int j = 0; j < 4; j++) oacc[i][j] = 0.f;

    for (int kv0 = 0; kv0 < SEQ; kv0 += 32) {
        int jmax = min(32, SEQ - kv0);

        {
            int r = tid >> 3, c8 = (tid & 7) * 8;
            float4 k0v = make_float4(0.f, 0.f, 0.f, 0.f);
            float4 k1v = make_float4(0.f, 0.f, 0.f, 0.f);
            if (r < jmax) {
                k0v = *(const float4*)&kh[(size_t)(kv0 + r) * HD + c8];
                k1v = *(const float4*)&kh[(size_t)(kv0 + r) * HD + c8 + 4];
            }
            *(float4*)&Ks[r][c8]     = k0v;
            *(float4*)&Ks[r][c8 + 4] = k1v;
        }
        {
            int kvr = tid & 31, dbase = (tid >> 5) * 8;
            float4 v0 = make_float4(0.f, 0.f, 0.f, 0.f);
            float4 v1 = make_float4(0.f, 0.f, 0.f, 0.f);
            if (kvr < jmax) {
                v0 = *(const float4*)&vh[(size_t)(kv0 + kvr) * HD + dbase];
                v1 = *(const float4*)&vh[(size_t)(kv0 + kvr) * HD + dbase + 4];
            }
            Vs[dbase + 0][kvr] = v0.x; Vs[dbase + 1][kvr] = v0.y;
            Vs[dbase + 2][kvr] = v0.z; Vs[dbase + 3][kvr] = v0.w;
            Vs[dbase + 4][kvr] = v1.x; Vs[dbase + 5][kvr] = v1.y;
            Vs[dbase + 6][kvr] = v1.z; Vs[dbase + 7][kvr] = v1.w;
        }
        __syncthreads();

        float sacc[2][4] = {};
#pragma unroll
        for (int ks = 0; ks < 8; ks++) {
            int kb = ks * 8;
#pragma unroll
            for (int nf = 0; nf < 2; nf++) {
                int n = wn16 + nf * 8 + gr;
                uint32_t bh[2], bl[2];
                split_tf32(Ks[n][kb + gc],     bh[0], bl[0]);
                split_tf32(Ks[n][kb + gc + 4], bh[1], bl[1]);
                mma_tf32(sacc[nf], q_hi[ks], bh);
                mma_tf32(sacc[nf], q_lo[ks], bh);
                mma_tf32(sacc[nf], q_hi[ks], bl);
            }
        }
#pragma unroll
        for (int nf = 0; nf < 2; nf++) {
            int n2 = wn16 + nf * 8 + gc * 2;
            Ps[wm + gr][n2]         = sacc[nf][0] * 0.125f;
            Ps[wm + gr][n2 + 1]     = sacc[nf][1] * 0.125f;
            Ps[wm + gr + 8][n2]     = sacc[nf][2] * 0.125f;
            Ps[wm + gr + 8][n2 + 1] = sacc[nf][3] * 0.125f;
        }
        __syncthreads();

        {
            int row = tid >> 2, qd = tid & 3;
            int jb = qd * 8;
            float mx = -1e30f;
#pragma unroll
            for (int j = 0; j < 8; j++)
                if (jb + j < jmax) mx = fmaxf(mx, Ps[row][jb + j]);
            mx = fmaxf(mx, __shfl_xor_sync(0xffffffffu, mx, 1));
            mx = fmaxf(mx, __shfl_xor_sync(0xffffffffu, mx, 2));
            float mo = ms[row];
            float mxn = fmaxf(mo, mx);
            float sum = 0.f;
#pragma unroll
            for (int j = 0; j < 8; j++) {
                float p = (jb + j < jmax) ? __expf(Ps[row][jb + j] - mxn) : 0.f;
                Ps[row][jb + j] = p;
                sum += p;
            }
            sum += __shfl_xor_sync(0xffffffffu, sum, 1);
            sum += __shfl_xor_sync(0xffffffffu, sum, 2);
            if (qd == 0) {
                float c = __expf(mo - mxn);
                ms[row] = mxn;
                ls[row] = ls[row] * c + sum;
                cs[row] = c;
            }
        }
        __syncthreads();

        {
            float c_lo = cs[wm + gr], c_hi = cs[wm + gr + 8];
#pragma unroll
            for (int nf = 0; nf < 4; nf++) {
                oacc[nf][0] *= c_lo; oacc[nf][1] *= c_lo;
                oacc[nf][2] *= c_hi; oacc[nf][3] *= c_hi;
            }
#pragma unroll
            for (int ks = 0; ks < 4; ks++) {
                int kb = ks * 8;
                uint32_t a_hi[4], a_lo[4];
                split_tf32(Ps[wm + gr][kb + gc],         a_hi[0], a_lo[0]);
                split_tf32(Ps[wm + gr + 8][kb + gc],     a_hi[1], a_lo[1]);
                split_tf32(Ps[wm + gr][kb + gc + 4],     a_hi[2], a_lo[2]);
                split_tf32(Ps[wm + gr + 8][kb + gc + 4], a_hi[3], a_lo[3]);
#pragma unroll
                for (int nf = 0; nf < 4; nf++) {
                    int n = wn32 + nf * 8 + gr;
                    uint32_t bh[2], bl[2];
                    split_tf32(Vs[n][kb + gc],     bh[0], bl[0]);
                    split_tf32(Vs[n][kb + gc + 4], bh[1], bl[1]);
                    mma_tf32(oacc[nf], a_hi, bh);
                    mma_tf32(oacc[nf], a_lo, bh);
                    mma_tf32(oacc[nf], a_hi, bl);
                }
            }
        }
        __syncthreads();
    }

    {
        float inv0 = 1.f / ls[wm + gr];
        float inv1 = 1.f / ls[wm + gr + 8];
        int s0 = q0 + wm + gr;
        int s1 = s0 + 8;
#pragma unroll
        for (int nf = 0; nf < 4; nf++) {
            int n2 = wn32 + nf * 8 + gc * 2;
            if (s0 < SEQ) {
                attn[(size_t)s0 * DIMV + h * HD + n2]     = oacc[nf][0] * inv0;
                attn[(size_t)s0 * DIMV + h * HD + n2 + 1] = oacc[nf][1] * inv0;
            }
            if (s1 < SEQ) {
                attn[(size_t)s1 * DIMV + h * HD + n2]     = oacc[nf][2] * inv1;
                attn[(size_t)s1 * DIMV + h * HD + n2 + 1] = oacc[nf][3] * inv1;
            }
        }
    }
}

// ---------------- conv1 (DIM->RANK, k=3, pad 1 over F=8) + exact GELU ----------------
__global__ void __launch_bounds__(128) conv1_gelu_kernel(
    const float* __restrict__ hidden, const float* __restrict__ w1,
    float* __restrict__ gel)
{
    __shared__ float xs[256][9];
    int p = blockIdx.x;
    int r = threadIdx.x;
    float acc[8] = {};
    for (int d0 = 0; d0 < DIMV; d0 += 256) {
        int dmax = min(256, DIMV - d0);
        for (int i = threadIdx.x; i < 2048; i += 128) {
            int d = i & 255, f = i >> 8;
            xs[d][f] = (d < dmax) ? hidden[(f * 256 + p) * DIMV + d0 + d] : 0.f;
        }
        __syncthreads();
#pragma unroll 2
        for (int d = 0; d < dmax; d++) {
            const float* w = w1 + r * (DIMV * 3) + (d0 + d) * 3;
            float w0 = w[0], wm = w[1], w2 = w[2];
            float xp[10];
            xp[0] = 0.f; xp[9] = 0.f;
#pragma unroll
            for (int f = 0; f < 8; f++) xp[f + 1] = xs[d][f];
#pragma unroll
            for (int f = 0; f < 8; f++)
                acc[f] += w0 * xp[f] + wm * xp[f + 1] + w2 * xp[f + 2];
        }
        __syncthreads();
    }
#pragma unroll
    for (int f = 0; f < 8; f++) {
        float x = acc[f];
        float g = 0.5f * x * (1.f + erff(x * 0.70710678118654752f));
        gel[(p * 128 + r) * 8 + f] = g;
    }
}

// ---------------- conv2 (RANK->DIM, k=3, pad 1) fused add into attn buffer ----------------
__global__ void __launch_bounds__(256) conv2_add_kernel(
    const float* __restrict__ w2, const float* __restrict__ gel,
    float* __restrict__ attn)
{
    __shared__ float gs[128][10];
    int p = blockIdx.x;
    int tid = threadIdx.x;
    for (int i = tid; i < 1024; i += 256) {
        int rr = i >> 3, f = i & 7;
        gs[rr][f + 1] = gel[(p * 128 + rr) * 8 + f];
    }
    if (tid < 128) { gs[tid][0] = 0.f; gs[tid][9] = 0.f; }
    __syncthreads();

    for (int d = tid; d < DIMV; d += 256) {
        float acc[8] = {};
        const float* w = w2 + d * 384;
#pragma unroll 2
        for (int rr = 0; rr < 128; rr++) {
            float w0 = w[rr * 3], wm = w[rr * 3 + 1], w2v = w[rr * 3 + 2];
#pragma unroll
            for (int f = 0; f < 8; f++)
                acc[f] += w0 * gs[rr][f] + wm * gs[rr][f + 1] + w2v * gs[rr][f + 2];
        }
#pragma unroll
        for (int f = 0; f < 8; f++) {
            int s = T_TXT + f * 256 + p;
            attn[s * DIMV + d] += acc[f];
        }
    }
}

// ---------------- launch ----------------
extern "C" void kernel_launch(void* const* d_in, const int* in_sizes, int n_in,
                              void* d_out, int out_size)
{
    const float* hidden = (const float*)d_in[0];
    const float* enc    = (const float*)d_in[1];
    const float* cosb   = (const float*)d_in[2];
    const float* sinb   = (const float*)d_in[3];
    const float* qw = (const float*)d_in[4];
    const float* qb = (const float*)d_in[5];
    const float* kw = (const float*)d_in[6];
    const float* kb = (const float*)d_in[7];
    const float* vw = (const float*)d_in[8];
    const float* vb = (const float*)d_in[9];
    const float* nqw = (const float*)d_in[10];
    const float* nqb = (const float*)d_in[11];
    const float* nkw = (const float*)d_in[12];
    const float* nkb = (const float*)d_in[13];
    const float* w1 = (const float*)d_in[14];
    const float* w2 = (const float*)d_in[15];
    const float* ow = (const float*)d_in[16];
    const float* ob = (const float*)d_in[17];

    float *hs, *q, *k, *v, *attn, *gel;
    cudaGetSymbolAddress((void**)&hs,   g_hs);
    cudaGetSymbolAddress((void**)&q,    g_q);
    cudaGetSymbolAddress((void**)&k,    g_k);
    cudaGetSymbolAddress((void**)&v,    g_v);
    cudaGetSymbolAddress((void**)&attn, g_attn);
    cudaGetSymbolAddress((void**)&gel,  g_gelu);

    cudaMemcpyAsync(hs, enc, (size_t)T_TXT * DIMV * sizeof(float),
                    cudaMemcpyDeviceToDevice, 0);
    cudaMemcpyAsync(hs + T_TXT * DIMV, hidden, (size_t)SVID * DIMV * sizeof(float),
                    cudaMemcpyDeviceToDevice, 0);

    dim3 gg((SEQ + 127) / 128, DIMV / 128);   // 18 x 15
    gemm_tf32<0><<<gg, 256>>>(hs, qw, qb, q, SEQ, DIMV, DIMV, 0);
    gemm_tf32<0><<<gg, 256>>>(hs, kw, kb, k, SEQ, DIMV, DIMV, 0);
    gemm_tf32<0><<<gg, 256>>>(hs, vw, vb, v, SEQ, DIMV, DIMV, 0);

    ln_rope_kernel<<<(2 * NH * SEQ + 3) / 4, 128>>>(q, k, cosb, sinb, nqw, nqb, nkw, nkb);

    attention_mma_kernel<<<dim3((SEQ + 63) / 64, NH), 256>>>(q, k, v, attn);

    conv1_gelu_kernel<<<256, 128>>>(hidden, w1, gel);
    conv2_add_kernel<<<256, 256>>>(w2, gel, attn);

    gemm_tf32<1><<<gg, 256>>>(attn, ow, ob, (float*)d_out, SEQ, DIMV, DIMV,
                              (long long)out_size);
}

// round 11
// speedup vs baseline: 1.0709x; 1.0663x over previous
#include <cuda_runtime.h>
#include <math.h>
#include <stdint.h>

#define DIMV 1920
#define T_TXT 226
#define SVID 2048
#define SEQ 2274
#define NH 30
#define HD 64

// ---------------- scratch (device globals; no allocation allowed) ----------------
__device__ float g_hs[SEQ * DIMV];        // concat(encoder, hidden)
__device__ float g_q[NH * SEQ * HD];      // head-major
__device__ float g_k[NH * SEQ * HD];
__device__ float g_v[NH * SEQ * HD];
__device__ float g_attn[SEQ * DIMV];      // attention output [s][dim] (+conv branch)
__device__ float g_gelu[256 * 128 * 8];   // conv1+gelu intermediate [p][r][f]

// ---------------- tf32 helpers ----------------
__device__ __forceinline__ uint32_t f2tf32(float x) {
    uint32_t r;
    asm("cvt.rna.tf32.f32 %0, %1;" : "=r"(r) : "f"(x));
    return r;
}
__device__ __forceinline__ void split_tf32(float x, uint32_t& hi, uint32_t& lo) {
    hi = f2tf32(x);
    lo = f2tf32(x - __uint_as_float(hi));
}
__device__ __forceinline__ void mma_tf32(float* d, const uint32_t* a, const uint32_t* b) {
    asm volatile(
        "mma.sync.aligned.m16n8k8.row.col.f32.tf32.tf32.f32 "
        "{%0,%1,%2,%3}, {%4,%5,%6,%7}, {%8,%9}, {%0,%1,%2,%3};"
        : "+f"(d[0]), "+f"(d[1]), "+f"(d[2]), "+f"(d[3])
        : "r"(a[0]), "r"(a[1]), "r"(a[2]), "r"(a[3]), "r"(b[0]), "r"(b[1]));
}

// ---------------- 3xTF32 tensor-core NT GEMM (round-5 compute + register prefetch) ----
// C = A(MxK) @ B(NxK)^T + bias
// MODE 0: head-major qkv epilogue; MODE 1: row-remap epilogue.
// Requires K % 32 == 0, N % 128 == 0 (holds: K=N=1920).
template <int MODE>
__global__ void __launch_bounds__(256) gemm_tf32(
    const float* __restrict__ A, const float* __restrict__ B,
    const float* __restrict__ bias, float* __restrict__ C,
    int M, int N, int K, long long out_limit)
{
    __shared__ __align__(16) float As[128][36];
    __shared__ __align__(16) float Bs[128][36];

    int tid  = threadIdx.x;
    int lane = tid & 31;
    int warp = tid >> 5;
    int wm = (warp >> 1) * 32;
    int wn = (warp & 1) * 64;
    int gr = lane >> 2;
    int gc = lane & 3;

    int m0 = blockIdx.x * 128, n0 = blockIdx.y * 128;

    float acc[2][8][4];
#pragma unroll
    for (int i = 0; i < 2; i++)
#pragma unroll
        for (int j = 0; j < 8; j++)
#pragma unroll
            for (int t = 0; t < 4; t++) acc[i][j][t] = 0.f;

    // register prefetch: 4 float4 per matrix per thread (128 rows x 32 k / 256 thr)
    float4 ra[4], rb[4];
#pragma unroll
    for (int i = 0; i < 4; i++) {
        int idx = tid + i * 256;
        int row = idx >> 3, c4 = idx & 7;
        ra[i] = make_float4(0.f, 0.f, 0.f, 0.f);
        if (m0 + row < M)
            ra[i] = *(const float4*)&A[(size_t)(m0 + row) * K + c4 * 4];
        rb[i] = *(const float4*)&B[(size_t)(n0 + row) * K + c4 * 4];
    }

    int NC = K / 32;
    for (int c = 0; c < NC; c++) {
        __syncthreads();   // previous chunk's compute done before smem overwrite
#pragma unroll
        for (int i = 0; i < 4; i++) {
            int idx = tid + i * 256;
            int row = idx >> 3, c4 = idx & 7;
            *(float4*)&As[row][c4 * 4] = ra[i];
            *(float4*)&Bs[row][c4 * 4] = rb[i];
        }
        __syncthreads();
        // issue next chunk's global loads; consumed after next top-of-loop sync
        if (c + 1 < NC) {
            int k0 = (c + 1) * 32;
#pragma unroll
            for (int i = 0; i < 4; i++) {
                int idx = tid + i * 256;
                int row = idx >> 3, c4 = idx & 7;
                ra[i] = make_float4(0.f, 0.f, 0.f, 0.f);
                if (m0 + row < M)
                    ra[i] = *(const float4*)&A[(size_t)(m0 + row) * K + k0 + c4 * 4];
                rb[i] = *(const float4*)&B[(size_t)(n0 + row) * K + k0 + c4 * 4];
            }
        }
        // compute: 4 k-steps of 8 (split-on-read, identical to round-5 best)
#pragma unroll
        for (int kk = 0; kk < 4; kk++) {
            int kb = kk * 8;
            uint32_t a_hi[2][4], a_lo[2][4];
#pragma unroll
            for (int mf = 0; mf < 2; mf++) {
                int r = wm + mf * 16 + gr;
                split_tf32(As[r][kb + gc],         a_hi[mf][0], a_lo[mf][0]);
                split_tf32(As[r + 8][kb + gc],     a_hi[mf][1], a_lo[mf][1]);
                split_tf32(As[r][kb + gc + 4],     a_hi[mf][2], a_lo[mf][2]);
                split_tf32(As[r + 8][kb + gc + 4], a_hi[mf][3], a_lo[mf][3]);
            }
            uint32_t b_hi[8][2], b_lo[8][2];
#pragma unroll
            for (int nf = 0; nf < 8; nf++) {
                int cc = wn + nf * 8 + gr;
                split_tf32(Bs[cc][kb + gc],     b_hi[nf][0], b_lo[nf][0]);
                split_tf32(Bs[cc][kb + gc + 4], b_hi[nf][1], b_lo[nf][1]);
            }
#pragma unroll
            for (int mf = 0; mf < 2; mf++)
#pragma unroll
                for (int nf = 0; nf < 8; nf++) {
                    mma_tf32(acc[mf][nf], a_hi[mf], b_hi[nf]);
                    mma_tf32(acc[mf][nf], a_lo[mf], b_hi[nf]);
                    mma_tf32(acc[mf][nf], a_hi[mf], b_lo[nf]);
                }
        }
    }

    // epilogue: fragment c0:(r,c) c1:(r,c+1) c2:(r+8,c) c3:(r+8,c+1)
#pragma unroll
    for (int mf = 0; mf < 2; mf++) {
        int rbase = m0 + wm + mf * 16 + gr;
#pragma unroll
        for (int nf = 0; nf < 8; nf++) {
            int cbase = n0 + wn + nf * 8 + gc * 2;
#pragma unroll
            for (int half = 0; half < 2; half++) {
                int m = rbase + half * 8;
                if (m >= M) continue;
#pragma unroll
                for (int jj = 0; jj < 2; jj++) {
                    int n = cbase + jj;
                    float val = acc[mf][nf][half * 2 + jj] + bias[n];
                    if (MODE == 0) {
                        C[((n >> 6) * SEQ + m) * 64 + (n & 63)] = val;
                    } else {
                        int r = (m >= T_TXT) ? (m - T_TXT) : (SVID + m);
                        long long idx = (long long)r * N + n;
                        if (idx < out_limit) C[idx] = val;
                    }
                }
            }
        }
    }
}

// ---------------- per-(head,pos) LayerNorm(HD=64) + RoPE on video rows ----------------
__global__ void __launch_bounds__(128) ln_rope_kernel(
    float* __restrict__ qbuf, float* __restrict__ kbuf,
    const float* __restrict__ cosb, const float* __restrict__ sinb,
    const float* __restrict__ nqw, const float* __restrict__ nqb,
    const float* __restrict__ nkw, const float* __restrict__ nkb)
{
    int warp = threadIdx.x >> 5, lane = threadIdx.x & 31;
    int row = blockIdx.x * 4 + warp;
    const int ROWS = NH * SEQ;
    if (row >= 2 * ROWS) return;
    int zk = (row >= ROWS) ? 1 : 0;
    int rem = zk ? (row - ROWS) : row;
    int s = rem % SEQ;
    float* x = (zk ? kbuf : qbuf) + rem * HD;
    const float* wgt = zk ? nkw : nqw;
    const float* bia = zk ? nkb : nqb;

    float v0 = x[2 * lane], v1 = x[2 * lane + 1];
    float sum = v0 + v1;
#pragma unroll
    for (int o = 16; o; o >>= 1) sum += __shfl_xor_sync(0xffffffffu, sum, o);
    float mu = sum * (1.f / 64.f);
    float d0 = v0 - mu, d1 = v1 - mu;
    float vs = d0 * d0 + d1 * d1;
#pragma unroll
    for (int o = 16; o; o >>= 1) vs += __shfl_xor_sync(0xffffffffu, vs, o);
    float rstd = rsqrtf(vs * (1.f / 64.f) + 1e-6f);
    float y0 = d0 * rstd * wgt[2 * lane] + bia[2 * lane];
    float y1 = d1 * rstd * wgt[2 * lane + 1] + bia[2 * lane + 1];
    if (s >= T_TXT) {
        int sv = s - T_TXT;
        float c0 = cosb[sv * HD + 2 * lane], c1 = cosb[sv * HD + 2 * lane + 1];
        float sn0 = sinb[sv * HD + 2 * lane], sn1 = sinb[sv * HD + 2 * lane + 1];
        float r0v = y0 * c0 - y1 * sn0;
        float r1v = y1 * c1 + y0 * sn1;
        y0 = r0v; y1 = r1v;
    }
    x[2 * lane] = y0;
    x[2 * lane + 1] = y1;
}

// ---------------- flash attention, 3xTF32 tensor cores, BQ=64 BKV=32 ----------------
__global__ void __launch_bounds__(256) attention_mma_kernel(
    const float* __restrict__ q, const float* __restrict__ k,
    const float* __restrict__ v, float* __restrict__ attn)
{
    __shared__ __align__(16) float Qs[64][68];   // [q][d]
    __shared__ __align__(16) float Ks[32][68];   // [kv][d]
    __shared__ __align__(16) float Vs[64][36];   // [d][kv]  (transposed)
    __shared__ __align__(16) float Ps[64][36];   // [q][kv]  scores / probs
    __shared__ float ms[64], ls[64], cs[64];

    int tid  = threadIdx.x;
    int lane = tid & 31;
    int warp = tid >> 5;
    int gr = lane >> 2;
    int gc = lane & 3;
    int wm   = (warp >> 1) * 16;
    int wn16 = (warp & 1) * 16;
    int wn32 = (warp & 1) * 32;

    int h  = blockIdx.y;
    int q0 = blockIdx.x * 64;
    const float* qh = q + (size_t)(h * SEQ) * HD;
    const float* kh = k + (size_t)(h * SEQ) * HD;
    const float* vh = v + (size_t)(h * SEQ) * HD;

    {
        int r = tid >> 2, c16 = (tid & 3) * 16;
#pragma unroll
        for (int j = 0; j < 4; j++) {
            float4 val = make_float4(0.f, 0.f, 0.f, 0.f);
            if (q0 + r < SEQ)
                val = *(const float4*)&qh[(size_t)(q0 + r) * HD + c16 + j * 4];
            *(float4*)&Qs[r][c16 + j * 4] = val;
        }
    }
    if (tid < 64) { ms[tid] = -1e30f; ls[tid] = 0.f; }
    __syncthreads();

    uint32_t q_hi[8][4], q_lo[8][4];
#pragma unroll
    for (int ks = 0; ks < 8; ks++) {
        int kb = ks * 8;
        split_tf32(Qs[wm + gr][kb + gc],         q_hi[ks][0], q_lo[ks][0]);
        split_tf32(Qs[wm + gr + 8][kb + gc],     q_hi[ks][1], q_lo[ks][1]);
        split_tf32(Qs[wm + gr][kb + gc + 4],     q_hi[ks][2], q_lo[ks][2]);
        split_tf32(Qs[wm + gr + 8][kb + gc + 4], q_hi[ks][3], q_lo[ks][3]);
    }

    float oacc[4][4];
#pragma unroll
    for (int i = 0; i < 4; i++)
#pragma unroll
        for (int j = 0; j < 4; j++) oacc[i][j] = 0.f;

    for (int kv0 = 0; kv0 < SEQ; kv0 += 32) {
        int jmax = min(32, SEQ - kv0);

        {
            int r = tid >> 3, c8 = (tid & 7) * 8;
            float4 k0v = make_float4(0.f, 0.f, 0.f, 0.f);
            float4 k1v = make_float4(0.f, 0.f, 0.f, 0.f);
            if (r < jmax) {
                k0v = *(const float4*)&kh[(size_t)(kv0 + r) * HD + c8];
                k1v = *(const float4*)&kh[(size_t)(kv0 + r) * HD + c8 + 4];
            }
            *(float4*)&Ks[r][c8]     = k0v;
            *(float4*)&Ks[r][c8 + 4] = k1v;
        }
        {
            int kvr = tid & 31, dbase = (tid >> 5) * 8;
            float4 v0 = make_float4(0.f, 0.f, 0.f, 0.f);
            float4 v1 = make_float4(0.f, 0.f, 0.f, 0.f);
            if (kvr < jmax) {
                v0 = *(const float4*)&vh[(size_t)(kv0 + kvr) * HD + dbase];
                v1 = *(const float4*)&vh[(size_t)(kv0 + kvr) * HD + dbase + 4];
            }
            Vs[dbase + 0][kvr] = v0.x; Vs[dbase + 1][kvr] = v0.y;
            Vs[dbase + 2][kvr] = v0.z; Vs[dbase + 3][kvr] = v0.w;
            Vs[dbase + 4][kvr] = v1.x; Vs[dbase + 5][kvr] = v1.y;
            Vs[dbase + 6][kvr] = v1.z; Vs[dbase + 7][kvr] = v1.w;
        }
        __syncthreads();

        float sacc[2][4] = {};
#pragma unroll
        for (int ks = 0; ks < 8; ks++) {
            int kb = ks * 8;
#pragma unroll
            for (int nf = 0; nf < 2; nf++) {
                int n = wn16 + nf * 8 + gr;
                uint32_t bh[2], bl[2];
                split_tf32(Ks[n][kb + gc],     bh[0], bl[0]);
                split_tf32(Ks[n][kb + gc + 4], bh[1], bl[1]);
                mma_tf32(sacc[nf], q_hi[ks], bh);
                mma_tf32(sacc[nf], q_lo[ks], bh);
                mma_tf32(sacc[nf], q_hi[ks], bl);
            }
        }
#pragma unroll
        for (int nf = 0; nf < 2; nf++) {
            int n2 = wn16 + nf * 8 + gc * 2;
            Ps[wm + gr][n2]         = sacc[nf][0] * 0.125f;
            Ps[wm + gr][n2 + 1]     = sacc[nf][1] * 0.125f;
            Ps[wm + gr + 8][n2]     = sacc[nf][2] * 0.125f;
            Ps[wm + gr + 8][n2 + 1] = sacc[nf][3] * 0.125f;
        }
        __syncthreads();

        {
            int row = tid >> 2, qd = tid & 3;
            int jb = qd * 8;
            float mx = -1e30f;
#pragma unroll
            for (int j = 0; j < 8; j++)
                if (jb + j < jmax) mx = fmaxf(mx, Ps[row][jb + j]);
            mx = fmaxf(mx, __shfl_xor_sync(0xffffffffu, mx, 1));
            mx = fmaxf(mx, __shfl_xor_sync(0xffffffffu, mx, 2));
            float mo = ms[row];
            float mxn = fmaxf(mo, mx);
            float sum = 0.f;
#pragma unroll
            for (int j = 0; j < 8; j++) {
                float p = (jb + j < jmax) ? __expf(Ps[row][jb + j] - mxn) : 0.f;
                Ps[row][jb + j] = p;
                sum += p;
            }
            sum += __shfl_xor_sync(0xffffffffu, sum, 1);
            sum += __shfl_xor_sync(0xffffffffu, sum, 2);
            if (qd == 0) {
                float c = __expf(mo - mxn);
                ms[row] = mxn;
                ls[row] = ls[row] * c + sum;
                cs[row] = c;
            }
        }
        __syncthreads();

        {
            float c_lo = cs[wm + gr], c_hi = cs[wm + gr + 8];
#pragma unroll
            for (int nf = 0; nf < 4; nf++) {
                oacc[nf][0] *= c_lo; oacc[nf][1] *= c_lo;
                oacc[nf][2] *= c_hi; oacc[nf][3] *= c_hi;
            }
#pragma unroll
            for (int ks = 0; ks < 4; ks++) {
                int kb = ks * 8;
                uint32_t a_hi[4], a_lo[4];
                split_tf32(Ps[wm + gr][kb + gc],         a_hi[0], a_lo[0]);
                split_tf32(Ps[wm + gr + 8][kb + gc],     a_hi[1], a_lo[1]);
                split_tf32(Ps[wm + gr][kb + gc + 4],     a_hi[2], a_lo[2]);
                split_tf32(Ps[wm + gr + 8][kb + gc + 4], a_hi[3], a_lo[3]);
#pragma unroll
                for (int nf = 0; nf < 4; nf++) {
                    int n = wn32 + nf * 8 + gr;
                    uint32_t bh[2], bl[2];
                    split_tf32(Vs[n][kb + gc],     bh[0], bl[0]);
                    split_tf32(Vs[n][kb + gc + 4], bh[1], bl[1]);
                    mma_tf32(oacc[nf], a_hi, bh);
                    mma_tf32(oacc[nf], a_lo, bh);
                    mma_tf32(oacc[nf], a_hi, bl);
                }
            }
        }
        __syncthreads();
    }

    {
        float inv0 = 1.f / ls[wm + gr];
        float inv1 = 1.f / ls[wm + gr + 8];
        int s0 = q0 + wm + gr;
        int s1 = s0 + 8;
#pragma unroll
        for (int nf = 0; nf < 4; nf++) {
            int n2 = wn32 + nf * 8 + gc * 2;
            if (s0 < SEQ) {
                attn[(size_t)s0 * DIMV + h * HD + n2]     = oacc[nf][0] * inv0;
                attn[(size_t)s0 * DIMV + h * HD + n2 + 1] = oacc[nf][1] * inv0;
            }
            if (s1 < SEQ) {
                attn[(size_t)s1 * DIMV + h * HD + n2]     = oacc[nf][2] * inv1;
                attn[(size_t)s1 * DIMV + h * HD + n2 + 1] = oacc[nf][3] * inv1;
            }
        }
    }
}

// ---------------- conv1 (DIM->RANK, k=3, pad 1 over F=8) + exact GELU ----------------
__global__ void __launch_bounds__(128) conv1_gelu_kernel(
    const float* __restrict__ hidden, const float* __restrict__ w1,
    float* __restrict__ gel)
{
    __shared__ float xs[256][9];
    int p = blockIdx.x;
    int r = threadIdx.x;
    float acc[8] = {};
    for (int d0 = 0; d0 < DIMV; d0 += 256) {
        int dmax = min(256, DIMV - d0);
        for (int i = threadIdx.x; i < 2048; i += 128) {
            int d = i & 255, f = i >> 8;
            xs[d][f] = (d < dmax) ? hidden[(f * 256 + p) * DIMV + d0 + d] : 0.f;
        }
        __syncthreads();
#pragma unroll 2
        for (int d = 0; d < dmax; d++) {
            const float* w = w1 + r * (DIMV * 3) + (d0 + d) * 3;
            float w0 = w[0], wm = w[1], w2 = w[2];
            float xp[10];
            xp[0] = 0.f; xp[9] = 0.f;
#pragma unroll
            for (int f = 0; f < 8; f++) xp[f + 1] = xs[d][f];
#pragma unroll
            for (int f = 0; f < 8; f++)
                acc[f] += w0 * xp[f] + wm * xp[f + 1] + w2 * xp[f + 2];
        }
        __syncthreads();
    }
#pragma unroll
    for (int f = 0; f < 8; f++) {
        float x = acc[f];
        float g = 0.5f * x * (1.f + erff(x * 0.70710678118654752f));
        gel[(p * 128 + r) * 8 + f] = g;
    }
}

// ---------------- conv2 (RANK->DIM, k=3, pad 1) fused add into attn buffer ----------------
__global__ void __launch_bounds__(256) conv2_add_kernel(
    const float* __restrict__ w2, const float* __restrict__ gel,
    float* __restrict__ attn)
{
    __shared__ float gs[128][10];
    int p = blockIdx.x;
    int tid = threadIdx.x;
    for (int i = tid; i < 1024; i += 256) {
        int rr = i >> 3, f = i & 7;
        gs[rr][f + 1] = gel[(p * 128 + rr) * 8 + f];
    }
    if (tid < 128) { gs[tid][0] = 0.f; gs[tid][9] = 0.f; }
    __syncthreads();

    for (int d = tid; d < DIMV; d += 256) {
        float acc[8] = {};
        const float* w = w2 + d * 384;
#pragma unroll 2
        for (int rr = 0; rr < 128; rr++) {
            float w0 = w[rr * 3], wm = w[rr * 3 + 1], w2v = w[rr * 3 + 2];
#pragma unroll
            for (int f = 0; f < 8; f++)
                acc[f] += w0 * gs[rr][f] + wm * gs[rr][f + 1] + w2v * gs[rr][f + 2];
        }
#pragma unroll
        for (int f = 0; f < 8; f++) {
            int s = T_TXT + f * 256 + p;
            attn[s * DIMV + d] += acc[f];
        }
    }
}

// ---------------- launch ----------------
extern "C" void kernel_launch(void* const* d_in, const int* in_sizes, int n_in,
                              void* d_out, int out_size)
{
    const float* hidden = (const float*)d_in[0];
    const float* enc    = (const float*)d_in[1];
    const float* cosb   = (const float*)d_in[2];
    const float* sinb   = (const float*)d_in[3];
    const float* qw = (const float*)d_in[4];
    const float* qb = (const float*)d_in[5];
    const float* kw = (const float*)d_in[6];
    const float* kb = (const float*)d_in[7];
    const float* vw = (const float*)d_in[8];
    const float* vb = (const float*)d_in[9];
    const float* nqw = (const float*)d_in[10];
    const float* nqb = (const float*)d_in[11];
    const float* nkw = (const float*)d_in[12];
    const float* nkb = (const float*)d_in[13];
    const float* w1 = (const float*)d_in[14];
    const float* w2 = (const float*)d_in[15];
    const float* ow = (const float*)d_in[16];
    const float* ob = (const float*)d_in[17];

    float *hs, *q, *k, *v, *attn, *gel;
    cudaGetSymbolAddress((void**)&hs,   g_hs);
    cudaGetSymbolAddress((void**)&q,    g_q);
    cudaGetSymbolAddress((void**)&k,    g_k);
    cudaGetSymbolAddress((void**)&v,    g_v);
    cudaGetSymbolAddress((void**)&attn, g_attn);
    cudaGetSymbolAddress((void**)&gel,  g_gelu);

    cudaMemcpyAsync(hs, enc, (size_t)T_TXT * DIMV * sizeof(float),
                    cudaMemcpyDeviceToDevice, 0);
    cudaMemcpyAsync(hs + T_TXT * DIMV, hidden, (size_t)SVID * DIMV * sizeof(float),
                    cudaMemcpyDeviceToDevice, 0);

    dim3 gg((SEQ + 127) / 128, DIMV / 128);   // 18 x 15
    gemm_tf32<0><<<gg, 256>>>(hs, qw, qb, q, SEQ, DIMV, DIMV, 0);
    gemm_tf32<0><<<gg, 256>>>(hs, kw, kb, k, SEQ, DIMV, DIMV, 0);
    gemm_tf32<0><<<gg, 256>>>(hs, vw, vb, v, SEQ, DIMV, DIMV, 0);

    ln_rope_kernel<<<(2 * NH * SEQ + 3) / 4, 128>>>(q, k, cosb, sinb, nqw, nqb, nkw, nkb);

    attention_mma_kernel<<<dim3((SEQ + 63) / 64, NH), 256>>>(q, k, v, attn);

    conv1_gelu_kernel<<<256, 128>>>(hidden, w1, gel);
    conv2_add_kernel<<<256, 256>>>(w2, gel, attn);

    gemm_tf32<1><<<gg, 256>>>(attn, ow, ob, (float*)d_out, SEQ, DIMV, DIMV,
                              (long long)out_size);
}

// round 14
// speedup vs baseline: 1.1574x; 1.0808x over previous
#include <cuda_runtime.h>
#include <math.h>
#include <stdint.h>

#define DIMV 1920
#define T_TXT 226
#define SVID 2048
#define SEQ 2274
#define NH 30
#define HD 64

// ---------------- scratch (device globals; no allocation allowed) ----------------
__device__ float g_hs[SEQ * DIMV];        // concat(encoder, hidden)
__device__ float g_q[NH * SEQ * HD];      // head-major
__device__ float g_k[NH * SEQ * HD];
__device__ float g_v[NH * SEQ * HD];
__device__ float g_attn[SEQ * DIMV];      // attention output [s][dim] (+conv branch)
__device__ float g_gelu[256 * 128 * 8];   // conv1+gelu intermediate [p][r][f]

// ---------------- tf32 helpers ----------------
__device__ __forceinline__ uint32_t f2tf32(float x) {
    uint32_t r;
    asm("cvt.rna.tf32.f32 %0, %1;" : "=r"(r) : "f"(x));
    return r;
}
__device__ __forceinline__ void split_tf32(float x, uint32_t& hi, uint32_t& lo) {
    hi = f2tf32(x);
    lo = f2tf32(x - __uint_as_float(hi));
}
__device__ __forceinline__ void mma_tf32(float* d, const uint32_t* a, const uint32_t* b) {
    asm volatile(
        "mma.sync.aligned.m16n8k8.row.col.f32.tf32.tf32.f32 "
        "{%0,%1,%2,%3}, {%4,%5,%6,%7}, {%8,%9}, {%0,%1,%2,%3};"
        : "+f"(d[0]), "+f"(d[1]), "+f"(d[2]), "+f"(d[3])
        : "r"(a[0]), "r"(a[1]), "r"(a[2]), "r"(a[3]), "r"(b[0]), "r"(b[1]));
}

// ---------------- 2-pass TF32 tensor-core NT GEMM ----------------
// C = A(MxK) @ B(NxK)^T + bias, computed as A_hi*B_hi + A_lo*B_hi
// (residual ~2^-12 relative; attention stays 3-pass).
// MODE 0: head-major qkv epilogue; MODE 1: row-remap epilogue.
// Requires K % 32 == 0, N % 128 == 0 (holds: K=N=1920).
template <int MODE>
__global__ void __launch_bounds__(256) gemm_tf32(
    const float* __restrict__ A, const float* __restrict__ B,
    const float* __restrict__ bias, float* __restrict__ C,
    int M, int N, int K, long long out_limit)
{
    __shared__ __align__(16) float As[128][36];
    __shared__ __align__(16) float Bs[128][36];

    int tid  = threadIdx.x;
    int lane = tid & 31;
    int warp = tid >> 5;
    int wm = (warp >> 1) * 32;
    int wn = (warp & 1) * 64;
    int gr = lane >> 2;
    int gc = lane & 3;

    int m0 = blockIdx.x * 128, n0 = blockIdx.y * 128;

    float acc[2][8][4];
#pragma unroll
    for (int i = 0; i < 2; i++)
#pragma unroll
        for (int j = 0; j < 8; j++)
#pragma unroll
            for (int t = 0; t < 4; t++) acc[i][j][t] = 0.f;

    // register prefetch: 4 float4 per matrix per thread (128 rows x 32 k / 256 thr)
    float4 ra[4], rb[4];
#pragma unroll
    for (int i = 0; i < 4; i++) {
        int idx = tid + i * 256;
        int row = idx >> 3, c4 = idx & 7;
        ra[i] = make_float4(0.f, 0.f, 0.f, 0.f);
        if (m0 + row < M)
            ra[i] = *(const float4*)&A[(size_t)(m0 + row) * K + c4 * 4];
        rb[i] = *(const float4*)&B[(size_t)(n0 + row) * K + c4 * 4];
    }

    int NC = K / 32;
    for (int c = 0; c < NC; c++) {
        __syncthreads();   // previous chunk's compute done before smem overwrite
#pragma unroll
        for (int i = 0; i < 4; i++) {
            int idx = tid + i * 256;
            int row = idx >> 3, c4 = idx & 7;
            *(float4*)&As[row][c4 * 4] = ra[i];
            *(float4*)&Bs[row][c4 * 4] = rb[i];
        }
        __syncthreads();
        // issue next chunk's global loads; consumed after next top-of-loop sync
        if (c + 1 < NC) {
            int k0 = (c + 1) * 32;
#pragma unroll
            for (int i = 0; i < 4; i++) {
                int idx = tid + i * 256;
                int row = idx >> 3, c4 = idx & 7;
                ra[i] = make_float4(0.f, 0.f, 0.f, 0.f);
                if (m0 + row < M)
                    ra[i] = *(const float4*)&A[(size_t)(m0 + row) * K + k0 + c4 * 4];
                rb[i] = *(const float4*)&B[(size_t)(n0 + row) * K + k0 + c4 * 4];
            }
        }
        // compute: 4 k-steps of 8; A split hi/lo, B hi only (2-pass)
#pragma unroll
        for (int kk = 0; kk < 4; kk++) {
            int kb = kk * 8;
            uint32_t a_hi[2][4], a_lo[2][4];
#pragma unroll
            for (int mf = 0; mf < 2; mf++) {
                int r = wm + mf * 16 + gr;
                split_tf32(As[r][kb + gc],         a_hi[mf][0], a_lo[mf][0]);
                split_tf32(As[r + 8][kb + gc],     a_hi[mf][1], a_lo[mf][1]);
                split_tf32(As[r][kb + gc + 4],     a_hi[mf][2], a_lo[mf][2]);
                split_tf32(As[r + 8][kb + gc + 4], a_hi[mf][3], a_lo[mf][3]);
            }
            uint32_t b_hi[8][2];
#pragma unroll
            for (int nf = 0; nf < 8; nf++) {
                int cc = wn + nf * 8 + gr;
                b_hi[nf][0] = f2tf32(Bs[cc][kb + gc]);
                b_hi[nf][1] = f2tf32(Bs[cc][kb + gc + 4]);
            }
#pragma unroll
            for (int mf = 0; mf < 2; mf++)
#pragma unroll
                for (int nf = 0; nf < 8; nf++) {
                    mma_tf32(acc[mf][nf], a_hi[mf], b_hi[nf]);
                    mma_tf32(acc[mf][nf], a_lo[mf], b_hi[nf]);
                }
        }
    }

    // epilogue: fragment c0:(r,c) c1:(r,c+1) c2:(r+8,c) c3:(r+8,c+1)
#pragma unroll
    for (int mf = 0; mf < 2; mf++) {
        int rbase = m0 + wm + mf * 16 + gr;
#pragma unroll
        for (int nf = 0; nf < 8; nf++) {
            int cbase = n0 + wn + nf * 8 + gc * 2;
#pragma unroll
            for (int half = 0; half < 2; half++) {
                int m = rbase + half * 8;
                if (m >= M) continue;
#pragma unroll
                for (int jj = 0; jj < 2; jj++) {
                    int n = cbase + jj;
                    float val = acc[mf][nf][half * 2 + jj] + bias[n];
                    if (MODE == 0) {
                        C[((n >> 6) * SEQ + m) * 64 + (n & 63)] = val;
                    } else {
                        int r = (m >= T_TXT) ? (m - T_TXT) : (SVID + m);
                        long long idx = (long long)r * N + n;
                        if (idx < out_limit) C[idx] = val;
                    }
                }
            }
        }
    }
}

// ---------------- per-(head,pos) LayerNorm(HD=64) + RoPE on video rows ----------------
__global__ void __launch_bounds__(128) ln_rope_kernel(
    float* __restrict__ qbuf, float* __restrict__ kbuf,
    const float* __restrict__ cosb, const float* __restrict__ sinb,
    const float* __restrict__ nqw, const float* __restrict__ nqb,
    const float* __restrict__ nkw, const float* __restrict__ nkb)
{
    int warp = threadIdx.x >> 5, lane = threadIdx.x & 31;
    int row = blockIdx.x * 4 + warp;
    const int ROWS = NH * SEQ;
    if (row >= 2 * ROWS) return;
    int zk = (row >= ROWS) ? 1 : 0;
    int rem = zk ? (row - ROWS) : row;
    int s = rem % SEQ;
    float* x = (zk ? kbuf : qbuf) + rem * HD;
    const float* wgt = zk ? nkw : nqw;
    const float* bia = zk ? nkb : nqb;

    float v0 = x[2 * lane], v1 = x[2 * lane + 1];
    float sum = v0 + v1;
#pragma unroll
    for (int o = 16; o; o >>= 1) sum += __shfl_xor_sync(0xffffffffu, sum, o);
    float mu = sum * (1.f / 64.f);
    float d0 = v0 - mu, d1 = v1 - mu;
    float vs = d0 * d0 + d1 * d1;
#pragma unroll
    for (int o = 16; o; o >>= 1) vs += __shfl_xor_sync(0xffffffffu, vs, o);
    float rstd = rsqrtf(vs * (1.f / 64.f) + 1e-6f);
    float y0 = d0 * rstd * wgt[2 * lane] + bia[2 * lane];
    float y1 = d1 * rstd * wgt[2 * lane + 1] + bia[2 * lane + 1];
    if (s >= T_TXT) {
        int sv = s - T_TXT;
        float c0 = cosb[sv * HD + 2 * lane], c1 = cosb[sv * HD + 2 * lane + 1];
        float sn0 = sinb[sv * HD + 2 * lane], sn1 = sinb[sv * HD + 2 * lane + 1];
        float r0v = y0 * c0 - y1 * sn0;
        float r1v = y1 * c1 + y0 * sn1;
        y0 = r0v; y1 = r1v;
    }
    x[2 * lane] = y0;
    x[2 * lane + 1] = y1;
}

// ---------------- flash attention, 3xTF32 tensor cores, BQ=64 BKV=32 ----------------
__global__ void __launch_bounds__(256) attention_mma_kernel(
    const float* __restrict__ q, const float* __restrict__ k,
    const float* __restrict__ v, float* __restrict__ attn)
{
    __shared__ __align__(16) float Qs[64][68];   // [q][d]
    __shared__ __align__(16) float Ks[32][68];   // [kv][d]
    __shared__ __align__(16) float Vs[64][36];   // [d][kv]  (transposed)
    __shared__ __align__(16) float Ps[64][36];   // [q][kv]  scores / probs
    __shared__ float ms[64], ls[64], cs[64];

    int tid  = threadIdx.x;
    int lane = tid & 31;
    int warp = tid >> 5;
    int gr = lane >> 2;
    int gc = lane & 3;
    int wm   = (warp >> 1) * 16;
    int wn16 = (warp & 1) * 16;
    int wn32 = (warp & 1) * 32;

    int h  = blockIdx.y;
    int q0 = blockIdx.x * 64;
    const float* qh = q + (size_t)(h * SEQ) * HD;
    const float* kh = k + (size_t)(h * SEQ) * HD;
    const float* vh = v + (size_t)(h * SEQ) * HD;

    {
        int r = tid >> 2, c16 = (tid & 3) * 16;
#pragma unroll
        for (int j = 0; j < 4; j++) {
            float4 val = make_float4(0.f, 0.f, 0.f, 0.f);
            if (q0 + r < SEQ)
                val = *(const float4*)&qh[(size_t)(q0 + r) * HD + c16 + j * 4];
            *(float4*)&Qs[r][c16 + j * 4] = val;
        }
    }
    if (tid < 64) { ms[tid] = -1e30f; ls[tid] = 0.f; }
    __syncthreads();

    uint32_t q_hi[8][4], q_lo[8][4];
#pragma unroll
    for (int ks = 0; ks < 8; ks++) {
        int kb = ks * 8;
        split_tf32(Qs[wm + gr][kb + gc],         q_hi[ks][0], q_lo[ks][0]);
        split_tf32(Qs[wm + gr + 8][kb + gc],     q_hi[ks][1], q_lo[ks][1]);
        split_tf32(Qs[wm + gr][kb + gc + 4],     q_hi[ks][2], q_lo[ks][2]);
        split_tf32(Qs[wm + gr + 8][kb + gc + 4], q_hi[ks][3], q_lo[ks][3]);
    }

    float oacc[4][4];
#pragma unroll
    for (int i = 0; i < 4; i++)
#pragma unroll
        for (int j = 0; j < 4; j++) oacc[i][j] = 0.f;

    for (int kv0 = 0; kv0 < SEQ; kv0 += 32) {
        int jmax = min(32, SEQ - kv0);

        {
            int r = tid >> 3, c8 = (tid & 7) * 8;
            float4 k0v = make_float4(0.f, 0.f, 0.f, 0.f);
            float4 k1v = make_float4(0.f, 0.f, 0.f, 0.f);
            if (r < jmax) {
                k0v = *(const float4*)&kh[(size_t)(kv0 + r) * HD + c8];
                k1v = *(const float4*)&kh[(size_t)(kv0 + r) * HD + c8 + 4];
            }
            *(float4*)&Ks[r][c8]     = k0v;
            *(float4*)&Ks[r][c8 + 4] = k1v;
        }
        {
            int kvr = tid & 31, dbase = (tid >> 5) * 8;
            float4 v0 = make_float4(0.f, 0.f, 0.f, 0.f);
            float4 v1 = make_float4(0.f, 0.f, 0.f, 0.f);
            if (kvr < jmax) {
                v0 = *(const float4*)&vh[(size_t)(kv0 + kvr) * HD + dbase];
                v1 = *(const float4*)&vh[(size_t)(kv0 + kvr) * HD + dbase + 4];
            }
            Vs[dbase + 0][kvr] = v0.x; Vs[dbase + 1][kvr] = v0.y;
            Vs[dbase + 2][kvr] = v0.z; Vs[dbase + 3][kvr] = v0.w;
            Vs[dbase + 4][kvr] = v1.x; Vs[dbase + 5][kvr] = v1.y;
            Vs[dbase + 6][kvr] = v1.z; Vs[dbase + 7][kvr] = v1.w;
        }
        __syncthreads();

        float sacc[2][4] = {};
#pragma unroll
        for (int ks = 0; ks < 8; ks++) {
            int kb = ks * 8;
#pragma unroll
            for (int nf = 0; nf < 2; nf++) {
                int n = wn16 + nf * 8 + gr;
                uint32_t bh[2], bl[2];
                split_tf32(Ks[n][kb + gc],     bh[0], bl[0]);
                split_tf32(Ks[n][kb + gc + 4], bh[1], bl[1]);
                mma_tf32(sacc[nf], q_hi[ks], bh);
                mma_tf32(sacc[nf], q_lo[ks], bh);
                mma_tf32(sacc[nf], q_hi[ks], bl);
            }
        }
#pragma unroll
        for (int nf = 0; nf < 2; nf++) {
            int n2 = wn16 + nf * 8 + gc * 2;
            Ps[wm + gr][n2]         = sacc[nf][0] * 0.125f;
            Ps[wm + gr][n2 + 1]     = sacc[nf][1] * 0.125f;
            Ps[wm + gr + 8][n2]     = sacc[nf][2] * 0.125f;
            Ps[wm + gr + 8][n2 + 1] = sacc[nf][3] * 0.125f;
        }
        __syncthreads();

        {
            int row = tid >> 2, qd = tid & 3;
            int jb = qd * 8;
            float mx = -1e30f;
#pragma unroll
            for (int j = 0; j < 8; j++)
                if (jb + j < jmax) mx = fmaxf(mx, Ps[row][jb + j]);
            mx = fmaxf(mx, __shfl_xor_sync(0xffffffffu, mx, 1));
            mx = fmaxf(mx, __shfl_xor_sync(0xffffffffu, mx, 2));
            float mo = ms[row];
            float mxn = fmaxf(mo, mx);
            float sum = 0.f;
#pragma unroll
            for (int j = 0; j < 8; j++) {
                float p = (jb + j < jmax) ? __expf(Ps[row][jb + j] - mxn) : 0.f;
                Ps[row][jb + j] = p;
                sum += p;
            }
            sum += __shfl_xor_sync(0xffffffffu, sum, 1);
            sum += __shfl_xor_sync(0xffffffffu, sum, 2);
            if (qd == 0) {
                float c = __expf(mo - mxn);
                ms[row] = mxn;
                ls[row] = ls[row] * c + sum;
                cs[row] = c;
            }
        }
        __syncthreads();

        {
            float c_lo = cs[wm + gr], c_hi = cs[wm + gr + 8];
#pragma unroll
            for (int nf = 0; nf < 4; nf++) {
                oacc[nf][0] *= c_lo; oacc[nf][1] *= c_lo;
                oacc[nf][2] *= c_hi; oacc[nf][3] *= c_hi;
            }
#pragma unroll
            for (int ks = 0; ks < 4; ks++) {
                int kb = ks * 8;
                uint32_t a_hi[4], a_lo[4];
                split_tf32(Ps[wm + gr][kb + gc],         a_hi[0], a_lo[0]);
                split_tf32(Ps[wm + gr + 8][kb + gc],     a_hi[1], a_lo[1]);
                split_tf32(Ps[wm + gr][kb + gc + 4],     a_hi[2], a_lo[2]);
                split_tf32(Ps[wm + gr + 8][kb + gc + 4], a_hi[3], a_lo[3]);
#pragma unroll
                for (int nf = 0; nf < 4; nf++) {
                    int n = wn32 + nf * 8 + gr;
                    uint32_t bh[2], bl[2];
                    split_tf32(Vs[n][kb + gc],     bh[0], bl[0]);
                    split_tf32(Vs[n][kb + gc + 4], bh[1], bl[1]);
                    mma_tf32(oacc[nf], a_hi, bh);
                    mma_tf32(oacc[nf], a_lo, bh);
                    mma_tf32(oacc[nf], a_hi, bl);
                }
            }
        }
        __syncthreads();
    }

    {
        float inv0 = 1.f / ls[wm + gr];
        float inv1 = 1.f / ls[wm + gr + 8];
        int s0 = q0 + wm + gr;
        int s1 = s0 + 8;
#pragma unroll
        for (int nf = 0; nf < 4; nf++) {
            int n2 = wn32 + nf * 8 + gc * 2;
            if (s0 < SEQ) {
                attn[(size_t)s0 * DIMV + h * HD + n2]     = oacc[nf][0] * inv0;
                attn[(size_t)s0 * DIMV + h * HD + n2 + 1] = oacc[nf][1] * inv0;
            }
            if (s1 < SEQ) {
                attn[(size_t)s1 * DIMV + h * HD + n2]     = oacc[nf][2] * inv1;
                attn[(size_t)s1 * DIMV + h * HD + n2 + 1] = oacc[nf][3] * inv1;
            }
        }
    }
}

// ---------------- conv1 (DIM->RANK, k=3, pad 1 over F=8) + exact GELU ----------------
__global__ void __launch_bounds__(128) conv1_gelu_kernel(
    const float* __restrict__ hidden, const float* __restrict__ w1,
    float* __restrict__ gel)
{
    __shared__ float xs[256][9];
    int p = blockIdx.x;
    int r = threadIdx.x;
    float acc[8] = {};
    for (int d0 = 0; d0 < DIMV; d0 += 256) {
        int dmax = min(256, DIMV - d0);
        for (int i = threadIdx.x; i < 2048; i += 128) {
            int d = i & 255, f = i >> 8;
            xs[d][f] = (d < dmax) ? hidden[(f * 256 + p) * DIMV + d0 + d] : 0.f;
        }
        __syncthreads();
#pragma unroll 2
        for (int d = 0; d < dmax; d++) {
            const float* w = w1 + r * (DIMV * 3) + (d0 + d) * 3;
            float w0 = w[0], wm = w[1], w2 = w[2];
            float xp[10];
            xp[0] = 0.f; xp[9] = 0.f;
#pragma unroll
            for (int f = 0; f < 8; f++) xp[f + 1] = xs[d][f];
#pragma unroll
            for (int f = 0; f < 8; f++)
                acc[f] += w0 * xp[f] + wm * xp[f + 1] + w2 * xp[f + 2];
        }
        __syncthreads();
    }
#pragma unroll
    for (int f = 0; f < 8; f++) {
        float x = acc[f];
        float g = 0.5f * x * (1.f + erff(x * 0.70710678118654752f));
        gel[(p * 128 + r) * 8 + f] = g;
    }
}

// ---------------- conv2 (RANK->DIM, k=3, pad 1) fused add into attn buffer ----------------
__global__ void __launch_bounds__(256) conv2_add_kernel(
    const float* __restrict__ w2, const float* __restrict__ gel,
    float* __restrict__ attn)
{
    __shared__ float gs[128][10];
    int p = blockIdx.x;
    int tid = threadIdx.x;
    for (int i = tid; i < 1024; i += 256) {
        int rr = i >> 3, f = i & 7;
        gs[rr][f + 1] = gel[(p * 128 + rr) * 8 + f];
    }
    if (tid < 128) { gs[tid][0] = 0.f; gs[tid][9] = 0.f; }
    __syncthreads();

    for (int d = tid; d < DIMV; d += 256) {
        float acc[8] = {};
        const float* w = w2 + d * 384;
#pragma unroll 2
        for (int rr = 0; rr < 128; rr++) {
            float w0 = w[rr * 3], wm = w[rr * 3 + 1], w2v = w[rr * 3 + 2];
#pragma unroll
            for (int f = 0; f < 8; f++)
                acc[f] += w0 * gs[rr][f] + wm * gs[rr][f + 1] + w2v * gs[rr][f + 2];
        }
#pragma unroll
        for (int f = 0; f < 8; f++) {
            int s = T_TXT + f * 256 + p;
            attn[s * DIMV + d] += acc[f];
        }
    }
}

// ---------------- launch ----------------
extern "C" void kernel_launch(void* const* d_in, const int* in_sizes, int n_in,
                              void* d_out, int out_size)
{
    const float* hidden = (const float*)d_in[0];
    const float* enc    = (const float*)d_in[1];
    const float* cosb   = (const float*)d_in[2];
    const float* sinb   = (const float*)d_in[3];
    const float* qw = (const float*)d_in[4];
    const float* qb = (const float*)d_in[5];
    const float* kw = (const float*)d_in[6];
    const float* kb = (const float*)d_in[7];
    const float* vw = (const float*)d_in[8];
    const float* vb = (const float*)d_in[9];
    const float* nqw = (const float*)d_in[10];
    const float* nqb = (const float*)d_in[11];
    const float* nkw = (const float*)d_in[12];
    const float* nkb = (const float*)d_in[13];
    const float* w1 = (const float*)d_in[14];
    const float* w2 = (const float*)d_in[15];
    const float* ow = (const float*)d_in[16];
    const float* ob = (const float*)d_in[17];

    float *hs, *q, *k, *v, *attn, *gel;
    cudaGetSymbolAddress((void**)&hs,   g_hs);
    cudaGetSymbolAddress((void**)&q,    g_q);
    cudaGetSymbolAddress((void**)&k,    g_k);
    cudaGetSymbolAddress((void**)&v,    g_v);
    cudaGetSymbolAddress((void**)&attn, g_attn);
    cudaGetSymbolAddress((void**)&gel,  g_gelu);

    cudaMemcpyAsync(hs, enc, (size_t)T_TXT * DIMV * sizeof(float),
                    cudaMemcpyDeviceToDevice, 0);
    cudaMemcpyAsync(hs + T_TXT * DIMV, hidden, (size_t)SVID * DIMV * sizeof(float),
                    cudaMemcpyDeviceToDevice, 0);

    dim3 gg((SEQ + 127) / 128, DIMV / 128);   // 18 x 15
    gemm_tf32<0><<<gg, 256>>>(hs, qw, qb, q, SEQ, DIMV, DIMV, 0);
    gemm_tf32<0><<<gg, 256>>>(hs, kw, kb, k, SEQ, DIMV, DIMV, 0);
    gemm_tf32<0><<<gg, 256>>>(hs, vw, vb, v, SEQ, DIMV, DIMV, 0);

    ln_rope_kernel<<<(2 * NH * SEQ + 3) / 4, 128>>>(q, k, cosb, sinb, nqw, nqb, nkw, nkb);

    attention_mma_kernel<<<dim3((SEQ + 63) / 64, NH), 256>>>(q, k, v, attn);

    conv1_gelu_kernel<<<256, 128>>>(hidden, w1, gel);
    conv2_add_kernel<<<256, 256>>>(w2, gel, attn);

    gemm_tf32<1><<<gg, 256>>>(attn, ow, ob, (float*)d_out, SEQ, DIMV, DIMV,
                              (long long)out_size);
}